// round 7
// baseline (speedup 1.0000x reference)
#include <cuda_runtime.h>
#include <cuda_bf16.h>
#include <math.h>
#include <stdint.h>

// Problem constants
#define R_NODES 10
#define HID 128
#define NE 36
#define BT 12800
#define NODE_F 1280
#define NTOT (BT * NODE_F)
#define LN_EPS 1e-5f
#define NI 4                            // instances per GAT CTA
#define GRID_GAT (BT / NI)              // 3200

__device__ float g_nf0[NTOT];
__device__ float g_nf1[NTOT];
// W pre-arranged in mma.sync B-fragment layout:
// [layer][head]{ hi: [wslot(8)][kc(8)][lane(32)] 16B chunks = 32KB, lo: +32KB }
__device__ __align__(16) uint8_t g_Wt[3 * 4 * 65536];

__constant__ int c_start[R_NODES + 1] = {0, 5, 8, 12, 15, 17, 22, 27, 31, 33, 36};
__constant__ int c_src[NE] = {
    9, 5, 6, 1, 0,   0, 2, 1,   5, 1, 3, 2,   2, 4, 3,   3, 4,
    6, 2, 0, 7, 5,   5, 9, 0, 7, 6,   6, 5, 8, 7,   7, 8,   6, 0, 9
};

__device__ __forceinline__ float gelu_exact(float v) {
    return 0.5f * v * (1.0f + erff(v * 0.70710678118654752440f));
}
__device__ __forceinline__ uint32_t smem_u32(const void* p) {
    uint32_t a;
    asm("{ .reg .u64 t; cvta.to.shared.u64 t, %1; cvt.u32.u64 %0, t; }" : "=r"(a) : "l"(p));
    return a;
}
__device__ __forceinline__ void ldsm_x4(uint32_t* r, uint32_t addr) {
    asm volatile("ldmatrix.sync.aligned.m8n8.x4.shared.b16 {%0,%1,%2,%3}, [%4];"
                 : "=r"(r[0]), "=r"(r[1]), "=r"(r[2]), "=r"(r[3]) : "r"(addr));
}
__device__ __forceinline__ void mma_bf16(float* d, const uint32_t* a, uint32_t b0, uint32_t b1) {
    asm volatile("mma.sync.aligned.m16n8k16.row.col.f32.bf16.bf16.f32 "
                 "{%0,%1,%2,%3}, {%4,%5,%6,%7}, {%8,%9}, {%0,%1,%2,%3};"
                 : "+f"(d[0]), "+f"(d[1]), "+f"(d[2]), "+f"(d[3])
                 : "r"(a[0]), "r"(a[1]), "r"(a[2]), "r"(a[3]), "r"(b0), "r"(b1));
}
__device__ __forceinline__ void split_bf16x2(float v0, float v1, uint32_t& hi, uint32_t& lo) {
    __nv_bfloat16 h0 = __float2bfloat16(v0);
    __nv_bfloat16 h1 = __float2bfloat16(v1);
    __nv_bfloat16 l0 = __float2bfloat16(v0 - __bfloat162float(h0));
    __nv_bfloat16 l1 = __float2bfloat16(v1 - __bfloat162float(h1));
    hi = (uint32_t)__bfloat16_as_ushort(h0) | ((uint32_t)__bfloat16_as_ushort(h1) << 16);
    lo = (uint32_t)__bfloat16_as_ushort(l0) | ((uint32_t)__bfloat16_as_ushort(l1) << 16);
}

// ---------------------------------------------------------------------------
// W prep: per-(wslot,kc,lane) B fragments, bf16 hi/lo.
// ---------------------------------------------------------------------------
__global__ void wt_kernel(const float* __restrict__ Wg) {
    int l = blockIdx.x >> 2, h = blockIdx.x & 3;
    uint8_t* base = g_Wt + (size_t)(l * 4 + h) * 65536;
    const float* W = Wg + l * 65536 + h * 128;   // W[k*512 + n]
    for (int c = threadIdx.x; c < 2048; c += 256) {
        int ws = c >> 8, kc = (c >> 5) & 7, lane = c & 31;
        int n0 = ws * 16 + (lane >> 2);
        int k0 = kc * 16 + 2 * (lane & 3);
        uint32_t hi[4], lo[4];
#pragma unroll
        for (int j = 0; j < 4; ++j) {
            int n = n0 + (j >> 1) * 8;
            int k = k0 + (j & 1) * 8;
            float w0 = W[k * 512 + n];
            float w1 = W[(k + 1) * 512 + n];
            split_bf16x2(w0, w1, hi[j], lo[j]);
        }
        *(uint4*)(base + c * 16)         = make_uint4(hi[0], hi[1], hi[2], hi[3]);
        *(uint4*)(base + 32768 + c * 16) = make_uint4(lo[0], lo[1], lo[2], lo[3]);
    }
}

// ---------------------------------------------------------------------------
// Encoder (unchanged)
// ---------------------------------------------------------------------------
__global__ void __launch_bounds__(256) encoder_kernel(
    const float* __restrict__ x, const float* __restrict__ Wenc,
    const float* __restrict__ benc, const float* __restrict__ gamma,
    const float* __restrict__ beta, float* __restrict__ nf_out,
    float* __restrict__ region_out)
{
    const int tid = threadIdx.x;
    const int lane = tid & 31;
    const int w4 = (tid >> 5) & 3;
    const int inst = tid >> 7;
    const long bt = (long)blockIdx.x * 2 + inst;
    const float* xr = x + bt * (R_NODES * 6);
    float* outp = nf_out + bt * NODE_F;
    float* regp = region_out ? region_out + bt * NODE_F : nullptr;

    for (int r = w4; r < R_NODES; r += 4) {
        float xv[6];
#pragma unroll
        for (int c = 0; c < 6; ++c) xv[c] = xr[r * 6 + c];
        float h[4];
#pragma unroll
        for (int j = 0; j < 4; ++j) {
            int k = lane + 32 * j;
            float a = benc[r * HID + k];
#pragma unroll
            for (int c = 0; c < 6; ++c) a = fmaf(xv[c], Wenc[(r * 6 + c) * HID + k], a);
            h[j] = a;
        }
        float s = h[0] + h[1] + h[2] + h[3];
        float sq = h[0]*h[0] + h[1]*h[1] + h[2]*h[2] + h[3]*h[3];
#pragma unroll
        for (int o = 16; o > 0; o >>= 1) {
            s  += __shfl_xor_sync(0xffffffffu, s, o);
            sq += __shfl_xor_sync(0xffffffffu, sq, o);
        }
        float mean = s * (1.0f / 128.0f);
        float var = sq * (1.0f / 128.0f) - mean * mean;
        float rstd = rsqrtf(var + LN_EPS);
#pragma unroll
        for (int j = 0; j < 4; ++j) {
            int k = lane + 32 * j;
            float v = (h[j] - mean) * rstd * gamma[r * HID + k] + beta[r * HID + k];
            float g = gelu_exact(v);
            outp[r * HID + k] = g;
            if (regp) regp[r * HID + k] = g;
        }
    }
}

// ---------------------------------------------------------------------------
// GAT layer: bf16 split-3 mma.sync, B from L2 (double-buffered reg prefetch),
// softmax fused into aggregation (2 syncs/head). NI=4, 256 thr, 3 CTAs/SM.
// smem byte map (69120):
//   0      A_hi  (10240)       10240  A_lo  (10240)
//   20480  xp    (40*132*4 = 21120)
//   41600  out   (40*128*4 = 20480)
//   62080  att   (4096)
//   66176  alsp  (8*40*4 = 1280)    67456  aldp (1280)
//   68736  csrc  (144)
// ---------------------------------------------------------------------------
#define A_LO_B   10240
#define XP_B     20480
#define OUT_B    41600
#define ATT_B    62080
#define ALSP_B   66176
#define ALDP_B   67456
#define CSRC_B   68736
#define SM_DYNBYTES 69120

__global__ void __launch_bounds__(256, 3) gat_mma_kernel(
    const float* __restrict__ nf_in, const uint8_t* __restrict__ Wt,
    const float* __restrict__ asrc, const float* __restrict__ adst,
    const float* __restrict__ bg, float* __restrict__ nf_out)
{
    extern __shared__ uint8_t smb[];
    const uint32_t sb = smem_u32(smb);
    float* s_xp    = (float*)(smb + XP_B);
    float* s_out   = (float*)(smb + OUT_B);
    float* s_att   = (float*)(smb + ATT_B);
    float* s_alsp  = (float*)(smb + ALSP_B);
    float* s_aldp  = (float*)(smb + ALDP_B);
    int*   s_csrc  = (int*)(smb + CSRC_B);

    const int tid  = threadIdx.x;
    const int wid  = tid >> 5;
    const int lane = tid & 31;
    const long blk = blockIdx.x;

    for (int i = tid; i < 512; i += 256) {
        s_att[i]       = asrc[i];
        s_att[512 + i] = adst[i];
    }
    if (tid < NE) s_csrc[tid] = c_src[tid];

    // A fill: 40 rows x 16 k-chunks = 640 tasks -> bf16 hi/lo swizzled
#pragma unroll
    for (int it = 0; it < 3; ++it) {
        int t = tid + 256 * it;
        if (t < 640) {
            int r = t >> 4, kb = t & 15;
            const float* src = nf_in + (blk * NI + r / R_NODES) * NODE_F + (r % R_NODES) * HID + kb * 8;
            float4 a = *(const float4*)(src);
            float4 b = *(const float4*)(src + 4);
            uint32_t hi[4], lo[4];
            split_bf16x2(a.x, a.y, hi[0], lo[0]);
            split_bf16x2(a.z, a.w, hi[1], lo[1]);
            split_bf16x2(b.x, b.y, hi[2], lo[2]);
            split_bf16x2(b.z, b.w, hi[3], lo[3]);
            uint32_t off = (uint32_t)(r * 256 + ((kb ^ (r & 7)) * 16));
            *(uint4*)(smb + off)          = make_uint4(hi[0], hi[1], hi[2], hi[3]);
            *(uint4*)(smb + A_LO_B + off) = make_uint4(lo[0], lo[1], lo[2], lo[3]);
        }
    }
    __syncthreads();

    // Per-warp/lane B fragment pointer (uint4 index)
    const uint4* Bp = (const uint4*)Wt + (wid * 256 + lane);

    const int q4 = lane >> 2;               // 0..7
    const int c2 = (lane & 3) * 2;
    const int cbase = wid * 16 + c2;

    // head-invariant aggregation indices (warp-uniform per iteration)
    int a_il[5], a_dst[5];
#pragma unroll
    for (int it = 0; it < 5; ++it) {
        int wq = wid * 32 + 256 * it;
        a_il[it]  = wq / 320;
        a_dst[it] = (wq - a_il[it] * 320) >> 5;
    }

    for (int h = 0; h < 4; ++h) {
        const uint4* Bh = Bp + h * 4096;

        // ---- GEMM: warp owns cols [wid*16,+16), 3 m-tiles; B double-buffered ----
        float acc[3][2][4];
#pragma unroll
        for (int mt = 0; mt < 3; ++mt)
#pragma unroll
            for (int nt = 0; nt < 2; ++nt)
#pragma unroll
                for (int j = 0; j < 4; ++j) acc[mt][nt][j] = 0.f;

        uint4 bh = Bh[0];
        uint4 bl = Bh[2048];
#pragma unroll
        for (int kc = 0; kc < 8; ++kc) {
            uint4 bhc = bh, blc = bl;
            if (kc < 7) {
                bh = Bh[(kc + 1) * 32];
                bl = Bh[(kc + 1) * 32 + 2048];
            }
            int m = lane >> 3, i2 = lane & 7;
            int kb = kc * 2 + (m >> 1);
            int rbase = (m & 1) * 8 + i2;
#pragma unroll
            for (int mt = 0; mt < 3; ++mt) {
                int r = mt * 16 + rbase;
                uint32_t addr = sb + (uint32_t)(r * 256 + ((kb ^ (r & 7)) * 16));
                uint32_t ahi[4], alo[4];
                ldsm_x4(ahi, addr);
                ldsm_x4(alo, addr + A_LO_B);
                mma_bf16(acc[mt][0], ahi, bhc.x, bhc.y);
                mma_bf16(acc[mt][1], ahi, bhc.z, bhc.w);
                mma_bf16(acc[mt][0], alo, bhc.x, bhc.y);
                mma_bf16(acc[mt][1], alo, bhc.z, bhc.w);
                mma_bf16(acc[mt][0], ahi, blc.x, blc.y);
                mma_bf16(acc[mt][1], ahi, blc.z, blc.w);
            }
        }

        // ---- xp store + logit partials straight from accumulators ----
        float pals[6], pald[6];
#pragma unroll
        for (int j = 0; j < 6; ++j) { pals[j] = 0.f; pald[j] = 0.f; }
#pragma unroll
        for (int mt = 0; mt < 3; ++mt) {
#pragma unroll
            for (int nt = 0; nt < 2; ++nt) {
                int cc = cbase + nt * 8;
                float a0 = s_att[h * 128 + cc],       a1 = s_att[h * 128 + cc + 1];
                float d0 = s_att[512 + h * 128 + cc], d1 = s_att[512 + h * 128 + cc + 1];
                pals[mt*2]   = fmaf(acc[mt][nt][0], a0, fmaf(acc[mt][nt][1], a1, pals[mt*2]));
                pald[mt*2]   = fmaf(acc[mt][nt][0], d0, fmaf(acc[mt][nt][1], d1, pald[mt*2]));
                pals[mt*2+1] = fmaf(acc[mt][nt][2], a0, fmaf(acc[mt][nt][3], a1, pals[mt*2+1]));
                pald[mt*2+1] = fmaf(acc[mt][nt][2], d0, fmaf(acc[mt][nt][3], d1, pald[mt*2+1]));
                int r0 = mt * 16 + q4;
                *(float2*)(s_xp + r0 * 132 + cc) = make_float2(acc[mt][nt][0], acc[mt][nt][1]);
                if (mt < 2)
                    *(float2*)(s_xp + (r0 + 8) * 132 + cc) = make_float2(acc[mt][nt][2], acc[mt][nt][3]);
            }
        }
#pragma unroll
        for (int j = 0; j < 6; ++j) {
            pals[j] += __shfl_xor_sync(0xffffffffu, pals[j], 1);
            pals[j] += __shfl_xor_sync(0xffffffffu, pals[j], 2);
            pald[j] += __shfl_xor_sync(0xffffffffu, pald[j], 1);
            pald[j] += __shfl_xor_sync(0xffffffffu, pald[j], 2);
        }
        if ((lane & 3) == 0) {
#pragma unroll
            for (int mt = 0; mt < 3; ++mt) {
                int r0 = mt * 16 + q4;
                s_alsp[wid * 40 + r0] = pals[mt * 2];
                s_aldp[wid * 40 + r0] = pald[mt * 2];
                if (mt < 2) {
                    s_alsp[wid * 40 + r0 + 8] = pals[mt * 2 + 1];
                    s_aldp[wid * 40 + r0 + 8] = pald[mt * 2 + 1];
                }
            }
        }
        __syncthreads();

        // ---- aggregation with inline per-warp segment softmax ----
#pragma unroll
        for (int it = 0; it < 5; ++it) {
            const int il = a_il[it], dst = a_dst[it], rb = il * 10;
            const int s0 = c_start[dst];
            const int deg = c_start[dst + 1] - s0;
            // ald(dst): broadcast reads, all lanes
            float ald = 0.f;
#pragma unroll
            for (int w = 0; w < 8; ++w) ald += s_aldp[w * 40 + rb + dst];
            // lane e < deg handles edge e
            int mysrc = s_csrc[s0 + (lane < deg ? lane : 0)];
            float v = -1e30f;
            if (lane < deg) {
                float als = 0.f;
#pragma unroll
                for (int w = 0; w < 8; ++w) als += s_alsp[w * 40 + rb + mysrc];
                v = als + ald;
                v = v > 0.f ? v : 0.2f * v;
            }
            // reduce max/sum over lanes 0..7 (deg <= 5)
            float m = v;
            m = fmaxf(m, __shfl_xor_sync(0xffffffffu, m, 1));
            m = fmaxf(m, __shfl_xor_sync(0xffffffffu, m, 2));
            m = fmaxf(m, __shfl_xor_sync(0xffffffffu, m, 4));
            float ex = (lane < deg) ? __expf(v - m) : 0.f;
            float ssum = ex;
            ssum += __shfl_xor_sync(0xffffffffu, ssum, 1);
            ssum += __shfl_xor_sync(0xffffffffu, ssum, 2);
            ssum += __shfl_xor_sync(0xffffffffu, ssum, 4);
            float myalpha = ex / ssum;

            const int q = tid + 256 * it;
            const int f = lane * 4;
            float4 a4;
            if (h == 0) { a4.x = a4.y = a4.z = a4.w = 0.f; }
            else          a4 = ((float4*)s_out)[q];
            for (int k = 0; k < deg; ++k) {
                float al = __shfl_sync(0xffffffffu, myalpha, k);
                int row = rb + s_csrc[s0 + k];
                float4 xv = *(const float4*)(s_xp + row * 132 + f);
                a4.x = fmaf(al, xv.x, a4.x);
                a4.y = fmaf(al, xv.y, a4.y);
                a4.z = fmaf(al, xv.z, a4.z);
                a4.w = fmaf(al, xv.w, a4.w);
            }
            ((float4*)s_out)[q] = a4;
        }
        __syncthreads();
    }

    // ---- epilogue: head mean + bias + GELU + residual ----
#pragma unroll
    for (int it = 0; it < 5; ++it) {
        const int il = a_il[it], dst = a_dst[it];
        const int q = tid + 256 * it;
        const int f = lane * 4;
        const long ig = blk * NI + il;
        float4 o = ((float4*)s_out)[q];
        float4 bgv = *(const float4*)(bg + f);
        float4 rs  = *(const float4*)(nf_in + ig * NODE_F + dst * HID + f);
        float4 w;
        w.x = gelu_exact(fmaf(0.25f, o.x, bgv.x)) + rs.x;
        w.y = gelu_exact(fmaf(0.25f, o.y, bgv.y)) + rs.y;
        w.z = gelu_exact(fmaf(0.25f, o.z, bgv.z)) + rs.z;
        w.w = gelu_exact(fmaf(0.25f, o.w, bgv.w)) + rs.w;
        *(float4*)(nf_out + ig * NODE_F + dst * HID + f) = w;
    }
}

// ---------------------------------------------------------------------------
extern "C" void kernel_launch(void* const* d_in, const int* in_sizes, int n_in,
                              void* d_out, int out_size)
{
    const float* x     = (const float*)d_in[0];
    const float* Wenc  = (const float*)d_in[1];
    const float* benc  = (const float*)d_in[2];
    const float* gamma = (const float*)d_in[3];
    const float* beta  = (const float*)d_in[4];
    const float* Wg    = (const float*)d_in[5];
    const float* asrc  = (const float*)d_in[6];
    const float* adst  = (const float*)d_in[7];
    const float* bg    = (const float*)d_in[8];

    float* out = (float*)d_out;
    float* region_out = (out_size >= 2 * NTOT) ? out + NTOT : nullptr;

    float* nf0;  cudaGetSymbolAddress((void**)&nf0, g_nf0);
    float* nf1;  cudaGetSymbolAddress((void**)&nf1, g_nf1);
    uint8_t* wt; cudaGetSymbolAddress((void**)&wt, g_Wt);

    cudaFuncSetAttribute(gat_mma_kernel, cudaFuncAttributeMaxDynamicSharedMemorySize, SM_DYNBYTES);

    wt_kernel<<<12, 256>>>(Wg);
    encoder_kernel<<<BT / 2, 256>>>(x, Wenc, benc, gamma, beta, nf0, region_out);

    gat_mma_kernel<<<GRID_GAT, 256, SM_DYNBYTES>>>(nf0, wt,               asrc,        adst,        bg,       nf1);
    gat_mma_kernel<<<GRID_GAT, 256, SM_DYNBYTES>>>(nf1, wt + 4 * 65536,   asrc + 512,  adst + 512,  bg + 128, nf0);
    gat_mma_kernel<<<GRID_GAT, 256, SM_DYNBYTES>>>(nf0, wt + 8 * 65536,   asrc + 1024, adst + 1024, bg + 256, out);
}

// round 8
// speedup vs baseline: 1.8573x; 1.8573x over previous
#include <cuda_runtime.h>
#include <cuda_bf16.h>
#include <math.h>
#include <stdint.h>

// Problem constants
#define R_NODES 10
#define HID 128
#define NE 36
#define BT 12800
#define NODE_F 1280
#define NTOT (BT * NODE_F)
#define LN_EPS 1e-5f
#define NI 4                            // instances per GAT CTA
#define GRID_GAT (BT / NI)              // 3200

__device__ float g_nf0[NTOT];
__device__ float g_nf1[NTOT];
// W pre-arranged in mma.sync B-fragment layout:
// [layer][head]{ hi: [wslot(8)][kc(8)][lane(32)] 16B chunks = 32KB, lo: +32KB }
__device__ __align__(16) uint8_t g_Wt[3 * 4 * 65536];

__constant__ int c_start[R_NODES + 1] = {0, 5, 8, 12, 15, 17, 22, 27, 31, 33, 36};
__constant__ int c_src[NE] = {
    9, 5, 6, 1, 0,   0, 2, 1,   5, 1, 3, 2,   2, 4, 3,   3, 4,
    6, 2, 0, 7, 5,   5, 9, 0, 7, 6,   6, 5, 8, 7,   7, 8,   6, 0, 9
};

__device__ __forceinline__ float gelu_exact(float v) {
    return 0.5f * v * (1.0f + erff(v * 0.70710678118654752440f));
}
__device__ __forceinline__ uint32_t smem_u32(const void* p) {
    uint32_t a;
    asm("{ .reg .u64 t; cvta.to.shared.u64 t, %1; cvt.u32.u64 %0, t; }" : "=r"(a) : "l"(p));
    return a;
}
__device__ __forceinline__ void ldsm_x4(uint32_t* r, uint32_t addr) {
    asm volatile("ldmatrix.sync.aligned.m8n8.x4.shared.b16 {%0,%1,%2,%3}, [%4];"
                 : "=r"(r[0]), "=r"(r[1]), "=r"(r[2]), "=r"(r[3]) : "r"(addr));
}
__device__ __forceinline__ void mma_bf16(float* d, const uint32_t* a, uint32_t b0, uint32_t b1) {
    asm volatile("mma.sync.aligned.m16n8k16.row.col.f32.bf16.bf16.f32 "
                 "{%0,%1,%2,%3}, {%4,%5,%6,%7}, {%8,%9}, {%0,%1,%2,%3};"
                 : "+f"(d[0]), "+f"(d[1]), "+f"(d[2]), "+f"(d[3])
                 : "r"(a[0]), "r"(a[1]), "r"(a[2]), "r"(a[3]), "r"(b0), "r"(b1));
}
__device__ __forceinline__ void split_bf16x2(float v0, float v1, uint32_t& hi, uint32_t& lo) {
    __nv_bfloat16 h0 = __float2bfloat16(v0);
    __nv_bfloat16 h1 = __float2bfloat16(v1);
    __nv_bfloat16 l0 = __float2bfloat16(v0 - __bfloat162float(h0));
    __nv_bfloat16 l1 = __float2bfloat16(v1 - __bfloat162float(h1));
    hi = (uint32_t)__bfloat16_as_ushort(h0) | ((uint32_t)__bfloat16_as_ushort(h1) << 16);
    lo = (uint32_t)__bfloat16_as_ushort(l0) | ((uint32_t)__bfloat16_as_ushort(l1) << 16);
}

// ---------------------------------------------------------------------------
// W prep: per-(wslot,kc,lane) B fragments, bf16 hi/lo.
// ---------------------------------------------------------------------------
__global__ void wt_kernel(const float* __restrict__ Wg) {
    int l = blockIdx.x >> 2, h = blockIdx.x & 3;
    uint8_t* base = g_Wt + (size_t)(l * 4 + h) * 65536;
    const float* W = Wg + l * 65536 + h * 128;   // W[k*512 + n]
    for (int c = threadIdx.x; c < 2048; c += 256) {
        int ws = c >> 8, kc = (c >> 5) & 7, lane = c & 31;
        int n0 = ws * 16 + (lane >> 2);
        int k0 = kc * 16 + 2 * (lane & 3);
        uint32_t hi[4], lo[4];
#pragma unroll
        for (int j = 0; j < 4; ++j) {
            int n = n0 + (j >> 1) * 8;
            int k = k0 + (j & 1) * 8;
            float w0 = W[k * 512 + n];
            float w1 = W[(k + 1) * 512 + n];
            split_bf16x2(w0, w1, hi[j], lo[j]);
        }
        *(uint4*)(base + c * 16)         = make_uint4(hi[0], hi[1], hi[2], hi[3]);
        *(uint4*)(base + 32768 + c * 16) = make_uint4(lo[0], lo[1], lo[2], lo[3]);
    }
}

// ---------------------------------------------------------------------------
// Encoder (unchanged)
// ---------------------------------------------------------------------------
__global__ void __launch_bounds__(256) encoder_kernel(
    const float* __restrict__ x, const float* __restrict__ Wenc,
    const float* __restrict__ benc, const float* __restrict__ gamma,
    const float* __restrict__ beta, float* __restrict__ nf_out,
    float* __restrict__ region_out)
{
    const int tid = threadIdx.x;
    const int lane = tid & 31;
    const int w4 = (tid >> 5) & 3;
    const int inst = tid >> 7;
    const long bt = (long)blockIdx.x * 2 + inst;
    const float* xr = x + bt * (R_NODES * 6);
    float* outp = nf_out + bt * NODE_F;
    float* regp = region_out ? region_out + bt * NODE_F : nullptr;

    for (int r = w4; r < R_NODES; r += 4) {
        float xv[6];
#pragma unroll
        for (int c = 0; c < 6; ++c) xv[c] = xr[r * 6 + c];
        float h[4];
#pragma unroll
        for (int j = 0; j < 4; ++j) {
            int k = lane + 32 * j;
            float a = benc[r * HID + k];
#pragma unroll
            for (int c = 0; c < 6; ++c) a = fmaf(xv[c], Wenc[(r * 6 + c) * HID + k], a);
            h[j] = a;
        }
        float s = h[0] + h[1] + h[2] + h[3];
        float sq = h[0]*h[0] + h[1]*h[1] + h[2]*h[2] + h[3]*h[3];
#pragma unroll
        for (int o = 16; o > 0; o >>= 1) {
            s  += __shfl_xor_sync(0xffffffffu, s, o);
            sq += __shfl_xor_sync(0xffffffffu, sq, o);
        }
        float mean = s * (1.0f / 128.0f);
        float var = sq * (1.0f / 128.0f) - mean * mean;
        float rstd = rsqrtf(var + LN_EPS);
#pragma unroll
        for (int j = 0; j < 4; ++j) {
            int k = lane + 32 * j;
            float v = (h[j] - mean) * rstd * gamma[r * HID + k] + beta[r * HID + k];
            float g = gelu_exact(v);
            outp[r * HID + k] = g;
            if (regp) regp[r * HID + k] = g;
        }
    }
}

// ---------------------------------------------------------------------------
// GAT layer: bf16 split-3 mma.sync. R5 structure (best), plus:
//  - register double-buffered B fragments across the kc loop
//  - hoisted A-address arithmetic
// NI=4, 256 threads, 3 CTAs/SM.
// smem byte map (69376):
//   0      A_hi  (10240)       10240  A_lo  (10240)
//   20480  xp    (40*132*4 = 21120)
//   41600  out   (40*128*4 = 20480)
//   62080  att   (4096)
//   66176  alsp  (8*40*4 = 1280)    67456  aldp (1280)
//   68736  alpha (4*36*4 = 576)
// ---------------------------------------------------------------------------
#define A_LO_B   10240
#define XP_B     20480
#define OUT_B    41600
#define ATT_B    62080
#define ALSP_B   66176
#define ALDP_B   67456
#define ALPHA_B  68736
#define SM_DYNBYTES 69376

__global__ void __launch_bounds__(256, 3) gat_mma_kernel(
    const float* __restrict__ nf_in, const uint8_t* __restrict__ Wt,
    const float* __restrict__ asrc, const float* __restrict__ adst,
    const float* __restrict__ bg, float* __restrict__ nf_out)
{
    extern __shared__ uint8_t smb[];
    const uint32_t sb = smem_u32(smb);
    float* s_xp    = (float*)(smb + XP_B);
    float* s_out   = (float*)(smb + OUT_B);
    float* s_att   = (float*)(smb + ATT_B);
    float* s_alsp  = (float*)(smb + ALSP_B);
    float* s_aldp  = (float*)(smb + ALDP_B);
    float* s_alpha = (float*)(smb + ALPHA_B);

    const int tid  = threadIdx.x;
    const int wid  = tid >> 5;
    const int lane = tid & 31;
    const long blk = blockIdx.x;

    for (int i = tid; i < 512; i += 256) {
        s_att[i]       = asrc[i];
        s_att[512 + i] = adst[i];
    }

    // A fill: 40 rows x 16 k-chunks = 640 tasks -> bf16 hi/lo swizzled
#pragma unroll
    for (int it = 0; it < 3; ++it) {
        int t = tid + 256 * it;
        if (t < 640) {
            int r = t >> 4, kb = t & 15;
            const float* src = nf_in + (blk * NI + r / R_NODES) * NODE_F + (r % R_NODES) * HID + kb * 8;
            float4 a = *(const float4*)(src);
            float4 b = *(const float4*)(src + 4);
            uint32_t hi[4], lo[4];
            split_bf16x2(a.x, a.y, hi[0], lo[0]);
            split_bf16x2(a.z, a.w, hi[1], lo[1]);
            split_bf16x2(b.x, b.y, hi[2], lo[2]);
            split_bf16x2(b.z, b.w, hi[3], lo[3]);
            uint32_t off = (uint32_t)(r * 256 + ((kb ^ (r & 7)) * 16));
            *(uint4*)(smb + off)          = make_uint4(hi[0], hi[1], hi[2], hi[3]);
            *(uint4*)(smb + A_LO_B + off) = make_uint4(lo[0], lo[1], lo[2], lo[3]);
        }
    }
    __syncthreads();

    // Per-warp/lane B fragment pointer (uint4 index)
    const uint4* Bp = (const uint4*)Wt + (wid * 256 + lane);

    const int q4 = lane >> 2;               // 0..7
    const int c2 = (lane & 3) * 2;
    const int cbase = wid * 16 + c2;

    // Hoisted A-fragment addressing (kc-dependent part is kb only)
    const int m_  = lane >> 3, i2_ = lane & 7;
    const int kbh = m_ >> 1;                       // kb = kc*2 + kbh
    const int rbase = (m_ & 1) * 8 + i2_;
    uint32_t arow[3];   // sb + r*256, r = mt*16 + rbase
    uint32_t rx7[3];    // (r & 7)
#pragma unroll
    for (int mt = 0; mt < 3; ++mt) {
        int r = mt * 16 + rbase;
        arow[mt] = sb + (uint32_t)(r * 256);
        rx7[mt]  = (uint32_t)(r & 7);
    }

    for (int h = 0; h < 4; ++h) {
        const uint4* Bh = Bp + h * 4096;

        // ---- GEMM: warp owns cols [wid*16,+16), 3 m-tiles; B double-buffered ----
        float acc[3][2][4];
#pragma unroll
        for (int mt = 0; mt < 3; ++mt)
#pragma unroll
            for (int nt = 0; nt < 2; ++nt)
#pragma unroll
                for (int j = 0; j < 4; ++j) acc[mt][nt][j] = 0.f;

        uint4 bh = Bh[0];
        uint4 bl = Bh[2048];
#pragma unroll
        for (int kc = 0; kc < 8; ++kc) {
            uint4 bhc = bh, blc = bl;
            if (kc < 7) {
                bh = Bh[(kc + 1) * 32];
                bl = Bh[(kc + 1) * 32 + 2048];
            }
            const uint32_t kb = (uint32_t)(kc * 2 + kbh);
#pragma unroll
            for (int mt = 0; mt < 3; ++mt) {
                uint32_t addr = arow[mt] + ((kb ^ rx7[mt]) << 4);
                uint32_t ahi[4], alo[4];
                ldsm_x4(ahi, addr);
                ldsm_x4(alo, addr + A_LO_B);
                mma_bf16(acc[mt][0], ahi, bhc.x, bhc.y);
                mma_bf16(acc[mt][1], ahi, bhc.z, bhc.w);
                mma_bf16(acc[mt][0], alo, bhc.x, bhc.y);
                mma_bf16(acc[mt][1], alo, bhc.z, bhc.w);
                mma_bf16(acc[mt][0], ahi, blc.x, blc.y);
                mma_bf16(acc[mt][1], ahi, blc.z, blc.w);
            }
        }

        // ---- xp store + logit partials straight from accumulators ----
        float pals[6], pald[6];
#pragma unroll
        for (int j = 0; j < 6; ++j) { pals[j] = 0.f; pald[j] = 0.f; }
#pragma unroll
        for (int mt = 0; mt < 3; ++mt) {
#pragma unroll
            for (int nt = 0; nt < 2; ++nt) {
                int cc = cbase + nt * 8;
                float a0 = s_att[h * 128 + cc],       a1 = s_att[h * 128 + cc + 1];
                float d0 = s_att[512 + h * 128 + cc], d1 = s_att[512 + h * 128 + cc + 1];
                pals[mt*2]   = fmaf(acc[mt][nt][0], a0, fmaf(acc[mt][nt][1], a1, pals[mt*2]));
                pald[mt*2]   = fmaf(acc[mt][nt][0], d0, fmaf(acc[mt][nt][1], d1, pald[mt*2]));
                pals[mt*2+1] = fmaf(acc[mt][nt][2], a0, fmaf(acc[mt][nt][3], a1, pals[mt*2+1]));
                pald[mt*2+1] = fmaf(acc[mt][nt][2], d0, fmaf(acc[mt][nt][3], d1, pald[mt*2+1]));
                int r0 = mt * 16 + q4;
                *(float2*)(s_xp + r0 * 132 + cc) = make_float2(acc[mt][nt][0], acc[mt][nt][1]);
                if (mt < 2)
                    *(float2*)(s_xp + (r0 + 8) * 132 + cc) = make_float2(acc[mt][nt][2], acc[mt][nt][3]);
            }
        }
#pragma unroll
        for (int j = 0; j < 6; ++j) {
            pals[j] += __shfl_xor_sync(0xffffffffu, pals[j], 1);
            pals[j] += __shfl_xor_sync(0xffffffffu, pals[j], 2);
            pald[j] += __shfl_xor_sync(0xffffffffu, pald[j], 1);
            pald[j] += __shfl_xor_sync(0xffffffffu, pald[j], 2);
        }
        if ((lane & 3) == 0) {
#pragma unroll
            for (int mt = 0; mt < 3; ++mt) {
                int r0 = mt * 16 + q4;
                s_alsp[wid * 40 + r0] = pals[mt * 2];
                s_aldp[wid * 40 + r0] = pald[mt * 2];
                if (mt < 2) {
                    s_alsp[wid * 40 + r0 + 8] = pals[mt * 2 + 1];
                    s_aldp[wid * 40 + r0 + 8] = pald[mt * 2 + 1];
                }
            }
        }
        __syncthreads();

        // ---- segment softmax (40 workers; reduce 8 warp-partials inline) ----
        if (tid < 40) {
            int il = tid / 10, dst = tid - il * 10, rb = il * 10;
            float ald = 0.f;
#pragma unroll
            for (int w = 0; w < 8; ++w) ald += s_aldp[w * 40 + rb + dst];
            int s0 = c_start[dst], s1 = c_start[dst + 1];
            float vb[5], m = -1e30f;
            for (int k = s0; k < s1; ++k) {
                float als = 0.f;
#pragma unroll
                for (int w = 0; w < 8; ++w) als += s_alsp[w * 40 + rb + c_src[k]];
                float v = als + ald;
                v = v > 0.f ? v : 0.2f * v;
                vb[k - s0] = v;
                m = fmaxf(m, v);
            }
            float ssum = 0.f;
            for (int k = s0; k < s1; ++k) {
                float ex = __expf(vb[k - s0] - m);
                ssum += ex;
                s_alpha[il * NE + k] = ex;
            }
            float inv = 1.0f / ssum;
            for (int k = s0; k < s1; ++k) s_alpha[il * NE + k] *= inv;
        }
        __syncthreads();

        // ---- aggregation (accumulate in s_out) ----
#pragma unroll
        for (int it = 0; it < 5; ++it) {
            int q = tid + 256 * it;                 // 1280 float4 tasks
            int il = q / 320, rem = q - il * 320, dst = rem >> 5, f = (rem & 31) * 4;
            float4 a4;
            if (h == 0) { a4.x = a4.y = a4.z = a4.w = 0.f; }
            else          a4 = ((float4*)s_out)[q];
            int s0 = c_start[dst], s1 = c_start[dst + 1];
            int rb = il * 10;
            for (int k = s0; k < s1; ++k) {
                int row = rb + c_src[k];
                float al = s_alpha[il * NE + k];
                float4 xv = *(const float4*)(s_xp + row * 132 + f);
                a4.x = fmaf(al, xv.x, a4.x);
                a4.y = fmaf(al, xv.y, a4.y);
                a4.z = fmaf(al, xv.z, a4.z);
                a4.w = fmaf(al, xv.w, a4.w);
            }
            ((float4*)s_out)[q] = a4;
        }
        __syncthreads();
    }

    // ---- epilogue: head mean + bias + GELU + residual ----
#pragma unroll
    for (int it = 0; it < 5; ++it) {
        int q = tid + 256 * it;
        int il = q / 320, rem = q - il * 320, dst = rem >> 5, f = (rem & 31) * 4;
        long ig = blk * NI + il;
        float4 o = ((float4*)s_out)[q];
        float4 bgv = *(const float4*)(bg + f);
        float4 rs  = *(const float4*)(nf_in + ig * NODE_F + dst * HID + f);
        float4 w;
        w.x = gelu_exact(fmaf(0.25f, o.x, bgv.x)) + rs.x;
        w.y = gelu_exact(fmaf(0.25f, o.y, bgv.y)) + rs.y;
        w.z = gelu_exact(fmaf(0.25f, o.z, bgv.z)) + rs.z;
        w.w = gelu_exact(fmaf(0.25f, o.w, bgv.w)) + rs.w;
        *(float4*)(nf_out + ig * NODE_F + dst * HID + f) = w;
    }
}

// ---------------------------------------------------------------------------
extern "C" void kernel_launch(void* const* d_in, const int* in_sizes, int n_in,
                              void* d_out, int out_size)
{
    const float* x     = (const float*)d_in[0];
    const float* Wenc  = (const float*)d_in[1];
    const float* benc  = (const float*)d_in[2];
    const float* gamma = (const float*)d_in[3];
    const float* beta  = (const float*)d_in[4];
    const float* Wg    = (const float*)d_in[5];
    const float* asrc  = (const float*)d_in[6];
    const float* adst  = (const float*)d_in[7];
    const float* bg    = (const float*)d_in[8];

    float* out = (float*)d_out;
    float* region_out = (out_size >= 2 * NTOT) ? out + NTOT : nullptr;

    float* nf0;  cudaGetSymbolAddress((void**)&nf0, g_nf0);
    float* nf1;  cudaGetSymbolAddress((void**)&nf1, g_nf1);
    uint8_t* wt; cudaGetSymbolAddress((void**)&wt, g_Wt);

    cudaFuncSetAttribute(gat_mma_kernel, cudaFuncAttributeMaxDynamicSharedMemorySize, SM_DYNBYTES);

    wt_kernel<<<12, 256>>>(Wg);
    encoder_kernel<<<BT / 2, 256>>>(x, Wenc, benc, gamma, beta, nf0, region_out);

    gat_mma_kernel<<<GRID_GAT, 256, SM_DYNBYTES>>>(nf0, wt,               asrc,        adst,        bg,       nf1);
    gat_mma_kernel<<<GRID_GAT, 256, SM_DYNBYTES>>>(nf1, wt + 4 * 65536,   asrc + 512,  adst + 512,  bg + 128, nf0);
    gat_mma_kernel<<<GRID_GAT, 256, SM_DYNBYTES>>>(nf0, wt + 8 * 65536,   asrc + 1024, adst + 1024, bg + 256, out);
}